// round 2
// baseline (speedup 1.0000x reference)
#include <cuda_runtime.h>
#include <cuda_bf16.h>
#include <cstdint>

// Problem constants (fixed by the reference).
#define HID   2048
#define KSEL  256
#define NTOK  16384   // 8 * 2048 tokens
#define NTHR  256

// Flag: 1 if input_ids buffer is int64, 0 if int32.
__device__ int g_ids64;

// ---------------------------------------------------------------------------
// Detect int32 vs int64 ids: view the id buffer as 32-bit words. Within the
// first NTOK words (safe for both layouts), odd words are all zero iff the
// buffer is little-endian int64 with values < 50257.
// ---------------------------------------------------------------------------
__global__ void detect_ids_kernel(const unsigned int* __restrict__ w) {
    __shared__ unsigned acc[NTHR];
    unsigned v = 0;
    for (int i = threadIdx.x; i < NTOK / 2; i += NTHR)
        v |= w[2 * i + 1];
    acc[threadIdx.x] = v;
    __syncthreads();
    for (int s = NTHR / 2; s > 0; s >>= 1) {
        if (threadIdx.x < s) acc[threadIdx.x] |= acc[threadIdx.x + s];
        __syncthreads();
    }
    if (threadIdx.x == 0) g_ids64 = (acc[0] == 0u) ? 1 : 0;
}

// Order-preserving float32 -> uint32 key (ascending float => ascending uint).
__device__ __forceinline__ unsigned f2key(float f) {
    unsigned u = __float_as_uint(f);
    return u ^ ((u & 0x80000000u) ? 0xFFFFFFFFu : 0x80000000u);
}
__device__ __forceinline__ float key2f(unsigned u) {
    unsigned b = (u & 0x80000000u) ? (u ^ 0x80000000u) : ~u;
    return __uint_as_float(b);
}

// ---------------------------------------------------------------------------
// One CTA per token: gather row, radix-select the 256th largest value key,
// compact survivors, rank-sort into the output (exact jax.lax.top_k order).
// ---------------------------------------------------------------------------
__global__ __launch_bounds__(NTHR) void topk_kernel(
    const void* __restrict__ ids_raw,
    const float* __restrict__ W,
    float* __restrict__ out_val,
    float* __restrict__ out_idx)   // indices stored AS FLOAT (output dtype f32)
{
    const int tok = blockIdx.x;
    const int tid = threadIdx.x;

    __shared__ unsigned hist[256];
    __shared__ unsigned s_prefix, s_rem;
    __shared__ unsigned long long sk[KSEL];   // composite keys of > T survivors
    __shared__ int eqIdx[HID];                // indices of == T elements
    __shared__ int cntG, cntE;

    if (tid == 0) { s_prefix = 0u; s_rem = KSEL; cntG = 0; cntE = 0; }

    // ---- gather one embedding row (coalesced float4) into registers ----
    long long id;
    if (g_ids64) id = ((const long long*)ids_raw)[tok];
    else         id = (long long)((const int*)ids_raw)[tok];

    const float4* row = (const float4*)(W + (size_t)id * HID);
    float4 a = __ldg(row + tid);
    float4 b = __ldg(row + tid + NTHR);

    unsigned key[8];
    key[0] = f2key(a.x); key[1] = f2key(a.y); key[2] = f2key(a.z); key[3] = f2key(a.w);
    key[4] = f2key(b.x); key[5] = f2key(b.y); key[6] = f2key(b.z); key[7] = f2key(b.w);

    __syncthreads();

    // ---- 4-pass radix select: find T = key value of the 256th largest ----
    for (int s = 24; s >= 0; s -= 8) {
        hist[tid] = 0u;
        __syncthreads();
        const unsigned prefix = s_prefix;
        const unsigned maskHi = (s == 24) ? 0u : (0xFFFFFFFFu << (s + 8));
        #pragma unroll
        for (int e = 0; e < 8; e++) {
            unsigned k2 = key[e];
            if ((k2 & maskHi) == prefix)
                atomicAdd(&hist[(k2 >> s) & 0xFFu], 1u);
        }
        __syncthreads();
        if (tid == 0) {
            unsigned rem = s_rem, c = 0;
            int bi = 256;
            do { --bi; c += hist[bi]; } while (c < rem && bi > 0);
            s_prefix = prefix | ((unsigned)bi << s);
            s_rem    = rem - (c - hist[bi]);
        }
        __syncthreads();
    }
    const unsigned T = s_prefix;    // exact key of the k-th largest (by value)
    const unsigned r = s_rem;       // how many == T elements to keep (>=1)

    // ---- compact: strictly-greater survivors + threshold-equal indices ----
    #pragma unroll
    for (int e = 0; e < 8; e++) {
        unsigned k2 = key[e];
        int idx = (e < 4) ? (tid * 4 + e) : ((tid + NTHR) * 4 + (e - 4));
        if (k2 > T) {
            int p = atomicAdd(&cntG, 1);
            sk[p] = ((unsigned long long)k2 << 32) | (unsigned)(~idx);
        } else if (k2 == T) {
            int p = atomicAdd(&cntE, 1);
            eqIdx[p] = idx;
        }
    }
    __syncthreads();

    const int m  = cntG;   // m = KSEL - r  (<= 255)
    const int ne = cntE;

    float* ov = out_val + (size_t)tok * KSEL;
    float* oi = out_idx + (size_t)tok * KSEL;

    // ---- rank-sort the strictly-greater survivors (unique 64-bit keys) ----
    if (tid < m) {
        const unsigned long long my = sk[tid];
        int rank = 0;
        for (int j = 0; j < m; j++)
            rank += (sk[j] > my);
        ov[rank] = key2f((unsigned)(my >> 32));
        oi[rank] = (float)((int)(~(unsigned)my));
    }

    // ---- threshold-equal elements: ascending index, fill slots [m, 256) ----
    const float tval = key2f(T);
    for (int t = tid; t < ne; t += NTHR) {
        int myi = eqIdx[t];
        int rank = 0;
        for (int j = 0; j < ne; j++)
            rank += (eqIdx[j] < myi);
        if (rank < (int)r) {
            ov[m + rank] = tval;
            oi[m + rank] = (float)myi;
        }
    }
}

// ---------------------------------------------------------------------------
// kernel_launch: inputs per metadata order: input_ids, W, k (k unused: 256).
// Output layout: [values fp32 : NTOK*KSEL][indices-as-f32 : NTOK*KSEL].
// ---------------------------------------------------------------------------
extern "C" void kernel_launch(void* const* d_in, const int* in_sizes, int n_in,
                              void* d_out, int out_size)
{
    const void*  ids = d_in[0];
    const float* W   = (const float*)d_in[1];

    float* out_val = (float*)d_out;
    float* out_idx = (float*)d_out + (size_t)NTOK * KSEL;

    detect_ids_kernel<<<1, NTHR>>>((const unsigned int*)ids);
    topk_kernel<<<NTOK, NTHR>>>(ids, W, out_val, out_idx);
}

// round 3
// speedup vs baseline: 1.5061x; 1.5061x over previous
#include <cuda_runtime.h>
#include <cuda_bf16.h>
#include <cstdint>

#define HID   2048
#define KSEL  256
#define NTOK  16384
#define NTHR  256
#define FULLW 0xFFFFFFFFu

__device__ int g_ids64;

// Detect int32 vs int64 ids (odd 32-bit words all zero => int64).
__global__ void detect_ids_kernel(const unsigned int* __restrict__ w) {
    __shared__ unsigned acc[NTHR];
    unsigned v = 0;
    for (int i = threadIdx.x; i < NTOK / 2; i += NTHR) v |= w[2 * i + 1];
    acc[threadIdx.x] = v;
    __syncthreads();
    for (int s = NTHR / 2; s > 0; s >>= 1) {
        if (threadIdx.x < s) acc[threadIdx.x] |= acc[threadIdx.x + s];
        __syncthreads();
    }
    if (threadIdx.x == 0) g_ids64 = (acc[0] == 0u) ? 1 : 0;
}

__device__ __forceinline__ unsigned f2key(float f) {
    unsigned u = __float_as_uint(f);
    return u ^ ((u & 0x80000000u) ? 0xFFFFFFFFu : 0x80000000u);
}
__device__ __forceinline__ float key2f(unsigned u) {
    unsigned b = (u & 0x80000000u) ? (u ^ 0x80000000u) : ~u;
    return __uint_as_float(b);
}

struct SmemT {
    union { unsigned hist[2048]; int eqIdx[2048]; } u;   // 8KB, time-shared
    unsigned long long sk[KSEL];                          // 2KB
    unsigned warpTot[8];
    unsigned s_prefix, s_rem;
    int cntG, cntE;
};

// One radix pass: histogram (atomics) + parallel suffix-scan to find the
// bucket containing the rem-th largest, narrowing s_prefix / s_rem.
template<int SHIFT, int BITS, bool FIRST>
__device__ __forceinline__ void radix_pass(SmemT& s, const unsigned key[8],
                                           int tid, int lane, int wrp)
{
    constexpr int BINS = 1 << BITS;
    constexpr int BPT  = BINS / NTHR;      // bins per thread (consecutive)
    #pragma unroll
    for (int i = 0; i < BPT; i++) s.u.hist[tid + i * NTHR] = 0u;
    __syncthreads();

    const unsigned prefix = s.s_prefix;
    const unsigned rem    = s.s_rem;

    #pragma unroll
    for (int e = 0; e < 8; e++) {
        unsigned k = key[e];
        bool part;
        if constexpr (FIRST) part = true;
        else part = ((k >> (SHIFT + BITS)) == (prefix >> (SHIFT + BITS)));
        if (part) atomicAdd(&s.u.hist[(k >> SHIFT) & (BINS - 1)], 1u);
    }
    __syncthreads();

    // Per-thread sum of its BPT consecutive bins.
    unsigned tsum = 0;
    #pragma unroll
    for (int i = 0; i < BPT; i++) tsum += s.u.hist[tid * BPT + i];

    // Warp suffix-inclusive scan (sum over lanes >= mine).
    unsigned sfx = tsum;
    #pragma unroll
    for (int off = 1; off < 32; off <<= 1) {
        unsigned y = __shfl_down_sync(FULLW, sfx, off);
        if (lane + off < 32) sfx += y;
    }
    if (lane == 0) s.warpTot[wrp] = sfx;
    __syncthreads();

    unsigned hiW = 0;
    #pragma unroll
    for (int w = 0; w < 8; w++) hiW += (w > wrp) ? s.warpTot[w] : 0u;

    // run = count of elements in bins strictly above my top bin.
    unsigned run = hiW + (sfx - tsum);
    #pragma unroll
    for (int i = BPT - 1; i >= 0; i--) {
        unsigned h = s.u.hist[tid * BPT + i];
        if (run < rem && rem <= run + h) {
            s.s_prefix = prefix | ((unsigned)(tid * BPT + i) << SHIFT);
            s.s_rem    = rem - run;
        }
        run += h;
    }
    __syncthreads();
}

__global__ __launch_bounds__(NTHR) void topk_kernel(
    const void* __restrict__ ids_raw,
    const float* __restrict__ W,
    float* __restrict__ out_val,
    float* __restrict__ out_idx)
{
    __shared__ SmemT s;
    const int tok  = blockIdx.x;
    const int tid  = threadIdx.x;
    const int lane = tid & 31;
    const int wrp  = tid >> 5;

    if (tid == 0) { s.s_prefix = 0u; s.s_rem = KSEL; s.cntG = 0; s.cntE = 0; }

    long long id;
    if (g_ids64) id = ((const long long*)ids_raw)[tok];
    else         id = (long long)((const int*)ids_raw)[tok];

    const float4* row = (const float4*)(W + (size_t)id * HID);
    float4 a = __ldg(row + tid);
    float4 b = __ldg(row + tid + NTHR);

    unsigned key[8];
    key[0] = f2key(a.x); key[1] = f2key(a.y); key[2] = f2key(a.z); key[3] = f2key(a.w);
    key[4] = f2key(b.x); key[5] = f2key(b.y); key[6] = f2key(b.z); key[7] = f2key(b.w);

    __syncthreads();

    // ---- 3-pass radix select (11 + 11 + 10 bits) ----
    radix_pass<21, 11, true >(s, key, tid, lane, wrp);
    radix_pass<10, 11, false>(s, key, tid, lane, wrp);
    radix_pass< 0, 10, false>(s, key, tid, lane, wrp);

    const unsigned T = s.s_prefix;   // exact key of the 256th largest
    const unsigned r = s.s_rem;      // # of == T elements to keep (>= 1)

    // ---- ballot-aggregated compaction ----
    #pragma unroll
    for (int e = 0; e < 8; e++) {
        unsigned k = key[e];
        int idx = (e < 4) ? (tid * 4 + e) : ((tid + NTHR) * 4 + (e - 4));
        bool g = (k > T), q = (k == T);
        unsigned mg = __ballot_sync(FULLW, g);
        unsigned mq = __ballot_sync(FULLW, q);
        int baseG = 0, baseE = 0;
        if (lane == 0) {
            if (mg) baseG = atomicAdd(&s.cntG, __popc(mg));
            if (mq) baseE = atomicAdd(&s.cntE, __popc(mq));
        }
        baseG = __shfl_sync(FULLW, baseG, 0);
        baseE = __shfl_sync(FULLW, baseE, 0);
        unsigned ltm = (1u << lane) - 1u;
        if (g) s.sk[baseG + __popc(mg & ltm)] =
                   ((unsigned long long)k << 32) | (unsigned)(~idx);
        if (q) s.u.eqIdx[baseE + __popc(mq & ltm)] = idx;
    }
    __syncthreads();

    const int m  = s.cntG;     // m = KSEL - r <= 255
    const int ne = s.cntE;

    if (tid >= m) s.sk[tid] = 0ULL;     // pad for the bitonic network
    __syncthreads();

    // ---- bitonic sort of 256 composite keys, descending ----
    unsigned long long v = s.sk[tid];

    // k = 2..32: all exchanges intra-warp (register shuffles).
    #pragma unroll
    for (int kk = 2; kk <= 32; kk <<= 1) {
        #pragma unroll
        for (int j = kk >> 1; j >= 1; j >>= 1) {
            bool keepL = ((tid & j) == 0) != ((tid & kk) != 0);
            unsigned long long o = __shfl_xor_sync(FULLW, v, j);
            v = ((o > v) == keepL) ? o : v;
        }
    }
    // k = 64, 128, 256: j >= 32 via smem, j <= 16 via shuffles.
    #pragma unroll
    for (int kk = 64; kk <= 256; kk <<= 1) {
        #pragma unroll
        for (int j = kk >> 1; j >= 32; j >>= 1) {
            s.sk[tid] = v;
            __syncthreads();
            unsigned long long o = s.sk[tid ^ j];
            bool keepL = ((tid & j) == 0) != ((tid & kk) != 0);
            v = ((o > v) == keepL) ? o : v;
            __syncthreads();
        }
        #pragma unroll
        for (int j = 16; j >= 1; j >>= 1) {
            bool keepL = ((tid & j) == 0) != ((tid & kk) != 0);
            unsigned long long o = __shfl_xor_sync(FULLW, v, j);
            v = ((o > v) == keepL) ? o : v;
        }
    }

    float* ov = out_val + (size_t)tok * KSEL;
    float* oi = out_idx + (size_t)tok * KSEL;

    if (tid < m) {
        ov[tid] = key2f((unsigned)(v >> 32));
        oi[tid] = (float)((int)(~(unsigned)v));
    }

    // ---- threshold-equal elements: ascending index fills [m, 256) ----
    const float tval = key2f(T);
    for (int t = tid; t < ne; t += NTHR) {
        int myi = s.u.eqIdx[t];
        int rank = 0;
        for (int j = 0; j < ne; j++) rank += (s.u.eqIdx[j] < myi);
        if (rank < (int)r) { ov[m + rank] = tval; oi[m + rank] = (float)myi; }
    }
}

extern "C" void kernel_launch(void* const* d_in, const int* in_sizes, int n_in,
                              void* d_out, int out_size)
{
    const void*  ids = d_in[0];
    const float* W   = (const float*)d_in[1];

    float* out_val = (float*)d_out;
    float* out_idx = (float*)d_out + (size_t)NTOK * KSEL;

    detect_ids_kernel<<<1, NTHR>>>((const unsigned int*)ids);
    topk_kernel<<<NTOK, NTHR>>>(ids, W, out_val, out_idx);
}

// round 4
// speedup vs baseline: 2.0363x; 1.3520x over previous
#include <cuda_runtime.h>
#include <cuda_bf16.h>
#include <cstdint>

#define HID   2048
#define KSEL  256
#define NTOK  16384
#define NTHR  256
#define FULLW 0xFFFFFFFFu

__device__ int g_ids64;

// Detect int32 vs int64 ids (odd 32-bit words all zero => int64).
__global__ void detect_ids_kernel(const unsigned int* __restrict__ w) {
    __shared__ unsigned acc[NTHR];
    unsigned v = 0;
    for (int i = threadIdx.x; i < NTOK / 2; i += NTHR) v |= w[2 * i + 1];
    acc[threadIdx.x] = v;
    __syncthreads();
    for (int s = NTHR / 2; s > 0; s >>= 1) {
        if (threadIdx.x < s) acc[threadIdx.x] |= acc[threadIdx.x + s];
        __syncthreads();
    }
    if (threadIdx.x == 0) g_ids64 = (acc[0] == 0u) ? 1 : 0;
}

__device__ __forceinline__ unsigned f2key(float f) {
    unsigned u = __float_as_uint(f);
    return u ^ ((u & 0x80000000u) ? 0xFFFFFFFFu : 0x80000000u);
}
__device__ __forceinline__ float key2f(unsigned u) {
    unsigned b = (u & 0x80000000u) ? (u ^ 0x80000000u) : ~u;
    return __uint_as_float(b);
}

struct SmemT {
    unsigned hist[2048];             // 8KB
    unsigned long long sk[KSEL];     // 2KB: final 256 composite keys
    unsigned long long cand[2048];   // 16KB: threshold-bucket candidates
    unsigned warpTot[8];
    unsigned s_b, s_rem;
    int cntG, cntN;
};

__global__ __launch_bounds__(NTHR, 6) void topk_kernel(
    const void* __restrict__ ids_raw,
    const float* __restrict__ W,
    float* __restrict__ out_val,
    float* __restrict__ out_idx)
{
    __shared__ SmemT s;
    const int tok  = blockIdx.x;
    const int tid  = threadIdx.x;
    const int lane = tid & 31;
    const int wrp  = tid >> 5;

    if (tid == 0) { s.cntG = 0; s.cntN = 0; }

    // ---- gather one embedding row (coalesced float4) ----
    long long id;
    if (g_ids64) id = ((const long long*)ids_raw)[tok];
    else         id = (long long)((const int*)ids_raw)[tok];

    const float4* row = (const float4*)(W + (size_t)id * HID);
    float4 a = __ldg(row + tid);
    float4 b = __ldg(row + tid + NTHR);

    unsigned key[8];
    key[0] = f2key(a.x); key[1] = f2key(a.y); key[2] = f2key(a.z); key[3] = f2key(a.w);
    key[4] = f2key(b.x); key[5] = f2key(b.y); key[6] = f2key(b.z); key[7] = f2key(b.w);

    // ---- single 11-bit radix pass on the top bits ----
    uint4 z = make_uint4(0u, 0u, 0u, 0u);
    ((uint4*)s.hist)[tid]        = z;
    ((uint4*)s.hist)[tid + NTHR] = z;
    __syncthreads();

    #pragma unroll
    for (int e = 0; e < 8; e++)
        atomicAdd(&s.hist[key[e] >> 21], 1u);
    __syncthreads();

    // Parallel suffix scan to locate the bucket holding the 256th largest.
    uint4 h0 = ((uint4*)s.hist)[tid * 2];
    uint4 h1 = ((uint4*)s.hist)[tid * 2 + 1];
    unsigned bins[8] = {h0.x, h0.y, h0.z, h0.w, h1.x, h1.y, h1.z, h1.w};
    unsigned tsum = 0;
    #pragma unroll
    for (int i = 0; i < 8; i++) tsum += bins[i];

    unsigned sfx = tsum;                           // sum over lanes >= mine
    #pragma unroll
    for (int off = 1; off < 32; off <<= 1) {
        unsigned y = __shfl_down_sync(FULLW, sfx, off);
        if (lane + off < 32) sfx += y;
    }
    if (lane == 0) s.warpTot[wrp] = sfx;
    __syncthreads();

    unsigned hiW = 0;
    #pragma unroll
    for (int w = 0; w < 8; w++) hiW += (w > wrp) ? s.warpTot[w] : 0u;

    unsigned run = hiW + (sfx - tsum);             // count in bins above my top bin
    #pragma unroll
    for (int i = 7; i >= 0; i--) {
        unsigned h = bins[i];
        if (run < KSEL && KSEL <= run + h) {
            s.s_b   = (unsigned)(tid * 8 + i);
            s.s_rem = KSEL - run;
        }
        run += h;
    }
    __syncthreads();

    const unsigned bsel = s.s_b;
    const unsigned rem  = s.s_rem;                 // 1..count(bucket)

    // ---- ballot-aggregated compaction: >bucket to sk, ==bucket to cand ----
    #pragma unroll
    for (int e = 0; e < 8; e++) {
        unsigned k = key[e];
        unsigned d = k >> 21;
        int idx = (e < 4) ? (tid * 4 + e) : ((tid + NTHR) * 4 + (e - 4));
        bool g = (d > bsel), q = (d == bsel);
        unsigned mg = __ballot_sync(FULLW, g);
        unsigned mq = __ballot_sync(FULLW, q);
        int baseG = 0, baseN = 0;
        if (lane == 0) {
            if (mg) baseG = atomicAdd(&s.cntG, __popc(mg));
            if (mq) baseN = atomicAdd(&s.cntN, __popc(mq));
        }
        baseG = __shfl_sync(FULLW, baseG, 0);
        baseN = __shfl_sync(FULLW, baseN, 0);
        unsigned ltm = (1u << lane) - 1u;
        unsigned long long comp = ((unsigned long long)k << 32) | (unsigned)(~idx);
        if (g) s.sk[baseG + __popc(mg & ltm)]   = comp;
        if (q) s.cand[baseN + __popc(mq & ltm)] = comp;
    }
    __syncthreads();

    const int nG = s.cntG;     // == KSEL - rem
    const int n1 = s.cntN;     // typically ~25; up to 2048 worst case

    // ---- exact rank-select the top `rem` candidates by composite key ----
    for (int t = tid; t < n1; t += NTHR) {
        unsigned long long my = s.cand[t];
        int rank = 0;
        for (int j = 0; j < n1; j++) rank += (s.cand[j] > my);
        if (rank < (int)rem) s.sk[nG + rank] = my;
    }
    __syncthreads();

    // ---- bitonic sort of 256 distinct composite keys, descending ----
    unsigned long long v = s.sk[tid];

    #pragma unroll
    for (int kk = 2; kk <= 32; kk <<= 1) {
        #pragma unroll
        for (int j = kk >> 1; j >= 1; j >>= 1) {
            bool keepL = ((tid & j) == 0) != ((tid & kk) != 0);
            unsigned long long o = __shfl_xor_sync(FULLW, v, j);
            v = ((o > v) == keepL) ? o : v;
        }
    }
    #pragma unroll
    for (int kk = 64; kk <= 256; kk <<= 1) {
        #pragma unroll
        for (int j = kk >> 1; j >= 32; j >>= 1) {
            s.sk[tid] = v;
            __syncthreads();
            unsigned long long o = s.sk[tid ^ j];
            bool keepL = ((tid & j) == 0) != ((tid & kk) != 0);
            v = ((o > v) == keepL) ? o : v;
            __syncthreads();
        }
        #pragma unroll
        for (int j = 16; j >= 1; j >>= 1) {
            bool keepL = ((tid & j) == 0) != ((tid & kk) != 0);
            unsigned long long o = __shfl_xor_sync(FULLW, v, j);
            v = ((o > v) == keepL) ? o : v;
        }
    }

    float* ov = out_val + (size_t)tok * KSEL;
    float* oi = out_idx + (size_t)tok * KSEL;
    ov[tid] = key2f((unsigned)(v >> 32));
    oi[tid] = (float)((int)(~(unsigned)v));
}

extern "C" void kernel_launch(void* const* d_in, const int* in_sizes, int n_in,
                              void* d_out, int out_size)
{
    const void*  ids = d_in[0];
    const float* W   = (const float*)d_in[1];

    float* out_val = (float*)d_out;
    float* out_idx = (float*)d_out + (size_t)NTOK * KSEL;

    detect_ids_kernel<<<1, NTHR>>>((const unsigned int*)ids);
    topk_kernel<<<NTOK, NTHR>>>(ids, W, out_val, out_idx);
}